// round 14
// baseline (speedup 1.0000x reference)
#include <cuda_runtime.h>
#include <cuda_fp16.h>
#include <cstdint>

// ---------------- problem constants ----------------
constexpr int N_NODES = 100000;
constexpr int N_EDGES = 1600000;
constexpr int C       = 128;      // feature width
constexpr int G       = 256;      // num graphs
constexpr int SCAN_B  = (N_NODES + 255) / 256;   // 391

// ---------------- scratch (static device globals) ----------
__device__ int    g_ideg[N_NODES];
__device__ int    g_off[N_NODES + 1];
__device__ int    g_epos[N_EDGES];                // per-edge slot within dst bucket
__device__ int    g_bsum[SCAN_B];
__device__ int    g_boff[SCAN_B];
__device__ float  g_dinv[N_NODES];
__device__ int2   g_csr[N_EDGES];                 // (src, w as float bits)
__device__ __half g_W_h[3 * C * C];               // fp16 weights (W0,W1,W2)
__device__ __half g_bufA_h[(size_t)N_NODES * C];  // agg output / GEMM input (fp16)
__device__ __half g_bufB_h[(size_t)N_NODES * C];  // GEMM output / gather operand (fp16)
__device__ float  g_pooled[G * C];
__device__ int    g_gstart[G + 1];

// ---------------- mma helpers ----------------
__device__ __forceinline__ void ldsm4(uint32_t& r0, uint32_t& r1, uint32_t& r2,
                                      uint32_t& r3, uint32_t addr) {
    asm volatile("ldmatrix.sync.aligned.m8n8.x4.shared.b16 {%0,%1,%2,%3}, [%4];"
                 : "=r"(r0), "=r"(r1), "=r"(r2), "=r"(r3) : "r"(addr));
}
__device__ __forceinline__ void ldsm4t(uint32_t& r0, uint32_t& r1, uint32_t& r2,
                                       uint32_t& r3, uint32_t addr) {
    asm volatile("ldmatrix.sync.aligned.m8n8.x4.trans.shared.b16 {%0,%1,%2,%3}, [%4];"
                 : "=r"(r0), "=r"(r1), "=r"(r2), "=r"(r3) : "r"(addr));
}
__device__ __forceinline__ void mma16816(float* d, uint32_t a0, uint32_t a1,
                                         uint32_t a2, uint32_t a3,
                                         uint32_t b0, uint32_t b1) {
    asm volatile("mma.sync.aligned.m16n8k16.row.col.f32.f16.f16.f32 "
                 "{%0,%1,%2,%3}, {%4,%5,%6,%7}, {%8,%9}, {%0,%1,%2,%3};"
                 : "+f"(d[0]), "+f"(d[1]), "+f"(d[2]), "+f"(d[3])
                 : "r"(a0), "r"(a1), "r"(a2), "r"(a3), "r"(b0), "r"(b1));
}

// fma of 8 halfs (uint4-packed) scaled by cw into acc[8]
__device__ __forceinline__ void fma8(float* acc, uint4 rv, float cw) {
    float2 v0 = __half22float2(*(__half2*)&rv.x);
    float2 v1 = __half22float2(*(__half2*)&rv.y);
    float2 v2 = __half22float2(*(__half2*)&rv.z);
    float2 v3 = __half22float2(*(__half2*)&rv.w);
    acc[0] = fmaf(cw, v0.x, acc[0]);
    acc[1] = fmaf(cw, v0.y, acc[1]);
    acc[2] = fmaf(cw, v1.x, acc[2]);
    acc[3] = fmaf(cw, v1.y, acc[3]);
    acc[4] = fmaf(cw, v2.x, acc[4]);
    acc[5] = fmaf(cw, v2.y, acc[5]);
    acc[6] = fmaf(cw, v3.x, acc[6]);
    acc[7] = fmaf(cw, v3.y, acc[7]);
}

// ---------------- weight pre-conversion (fp32 -> fp16, once) --------------
__global__ void __launch_bounds__(256)
k_wconv(const float* __restrict__ W0, const float* __restrict__ W1,
        const float* __restrict__ W2)
{
    int idx4 = blockIdx.x * 256 + threadIdx.x;     // float4 index, 3*4096 total
    if (idx4 >= 3 * 4096) return;
    int mat = idx4 >> 12;
    int loc = idx4 & 4095;
    const float* W = (mat == 0) ? W0 : (mat == 1) ? W1 : W2;
    float4 v = ((const float4*)W)[loc];
    __half2 h0 = __floats2half2_rn(v.x, v.y);
    __half2 h1 = __floats2half2_rn(v.z, v.w);
    uint2 st; st.x = *(unsigned*)&h0; st.y = *(unsigned*)&h1;
    *(uint2*)(g_W_h + mat * C * C + loc * 4) = st;
}

// ---------------- CSR build ----------------
__global__ void k_init() {
    int i = blockIdx.x * blockDim.x + threadIdx.x;
    if (i < N_NODES) g_ideg[i] = 0;
}

__global__ void k_deg_count(const int* __restrict__ dst) {
    int e = blockIdx.x * blockDim.x + threadIdx.x;
    if (e < N_EDGES) g_epos[e] = atomicAdd(&g_ideg[dst[e]], 1);
}

// block-reduce degrees -> bsum; fused dinv; fused per-graph bounds search
// (the 257 binary searches hide their dependent-load latency among the
//  100k working threads of this grid, instead of serializing a 1-block kernel)
__global__ void __launch_bounds__(256) k_scan1(const int* __restrict__ batch) {
    __shared__ int sm[256];
    int t = threadIdx.x;
    int idx = blockIdx.x * 256 + t;
    int v = 0;
    if (idx < N_NODES) {
        v = g_ideg[idx];
        g_dinv[idx] = rsqrtf((float)(v + 1));
    }
    if (idx <= G) {
        if (idx == G) g_gstart[G] = N_NODES;
        else {
            int lo = 0, hi = N_NODES;
            while (lo < hi) {
                int mid = (lo + hi) >> 1;
                if (batch[mid] < idx) lo = mid + 1; else hi = mid;
            }
            g_gstart[idx] = lo;
        }
    }
    sm[t] = v;
    __syncthreads();
    #pragma unroll
    for (int s = 128; s > 0; s >>= 1) {
        if (t < s) sm[t] += sm[t + s];
        __syncthreads();
    }
    if (t == 0) g_bsum[blockIdx.x] = sm[0];
}

// pure scan of 391 block sums
__global__ void __launch_bounds__(512) k_scan2() {
    __shared__ int sm[512];
    int t = threadIdx.x;
    sm[t] = (t < SCAN_B) ? g_bsum[t] : 0;
    __syncthreads();
    #pragma unroll
    for (int d = 1; d < 512; d <<= 1) {
        int v = (t >= d) ? sm[t - d] : 0;
        __syncthreads();
        sm[t] += v;
        __syncthreads();
    }
    if (t < SCAN_B) g_boff[t] = (t == 0) ? 0 : sm[t - 1];
}

__global__ void __launch_bounds__(256) k_scan3() {
    __shared__ int sm[256];
    int t = threadIdx.x;
    int idx = blockIdx.x * 256 + t;
    int v = (idx < N_NODES) ? g_ideg[idx] : 0;
    sm[t] = v;
    __syncthreads();
    #pragma unroll
    for (int d = 1; d < 256; d <<= 1) {
        int u = (t >= d) ? sm[t - d] : 0;
        __syncthreads();
        sm[t] += u;
        __syncthreads();
    }
    if (idx < N_NODES) g_off[idx] = g_boff[blockIdx.x] + sm[t] - v;
    if (idx == 0) g_off[N_NODES] = N_EDGES;
}

__global__ void k_scatter(const int* __restrict__ src, const int* __restrict__ dst) {
    int e = blockIdx.x * blockDim.x + threadIdx.x;
    if (e >= N_EDGES) return;
    int s = src[e], d = dst[e];
    int pos = g_off[d] + g_epos[e];
    g_csr[pos] = make_int2(s, __float_as_int(g_dinv[s] * g_dinv[d]));
}

// ---------------- tensor-core GEMM -----------------------------------------
constexpr int LDA    = 136;
constexpr int GEMM_M = 256;
constexpr size_t GEMM_SMEM = (size_t)((256 + 128) * LDA) * sizeof(__half);

__global__ void __launch_bounds__(512)
k_gemm(const float* __restrict__ Aext, const float* __restrict__ bias,
       int wsel, int use_ext)
{
    extern __shared__ __half smh[];
    __half* As = smh;               // [256][LDA]
    __half* Ws = smh + 256 * LDA;   // [128][LDA]

    const int tid  = threadIdx.x;
    const int row0 = blockIdx.x * GEMM_M;
    const __half* Wh = g_W_h + wsel * C * C;

    {
        const uint4* W4 = (const uint4*)Wh;
        #pragma unroll
        for (int i = 0; i < 4; i++) {
            int idx = i * 512 + tid;
            int h   = idx * 8;
            int k   = h >> 7, n = h & 127;
            *(uint4*)(Ws + k * LDA + n) = W4[idx];
        }
    }
    if (use_ext) {
        const float4* A4 = (const float4*)Aext;
        #pragma unroll
        for (int i = 0; i < 16; i++) {
            int f4 = i * 512 + tid;
            int f  = f4 * 4;
            int r  = f >> 7, c = f & 127;
            int row = row0 + r;
            float4 v = make_float4(0.f, 0.f, 0.f, 0.f);
            if (row < N_NODES) v = A4[(size_t)row * 32 + (c >> 2)];
            __half2 h0 = __floats2half2_rn(v.x, v.y);
            __half2 h1 = __floats2half2_rn(v.z, v.w);
            uint2 st; st.x = *(unsigned*)&h0; st.y = *(unsigned*)&h1;
            *(uint2*)(As + r * LDA + c) = st;
        }
    } else {
        #pragma unroll
        for (int i = 0; i < 16; i++) {
            int f4 = i * 512 + tid;
            int f  = f4 * 4;
            int r  = f >> 7, c = f & 127;
            int row = row0 + r;
            float4 v = make_float4(0.f, 0.f, 0.f, 0.f);
            if (row < N_NODES) {
                uint2 raw = *(const uint2*)(g_bufA_h + (size_t)row * C + c);
                float2 p0 = __half22float2(*(__half2*)&raw.x);
                float2 p1 = __half22float2(*(__half2*)&raw.y);
                float4 bb = *(const float4*)(bias + c);
                v.x = fmaxf(p0.x + bb.x, 0.f);
                v.y = fmaxf(p0.y + bb.y, 0.f);
                v.z = fmaxf(p1.x + bb.z, 0.f);
                v.w = fmaxf(p1.y + bb.w, 0.f);
            }
            __half2 h0 = __floats2half2_rn(v.x, v.y);
            __half2 h1 = __floats2half2_rn(v.z, v.w);
            uint2 st; st.x = *(unsigned*)&h0; st.y = *(unsigned*)&h1;
            *(uint2*)(As + r * LDA + c) = st;
        }
    }
    __syncthreads();

    const int w    = tid >> 5;
    const int lane = tid & 31;
    const int quad = lane >> 3, r8 = lane & 7;

    uint32_t sA = (uint32_t)__cvta_generic_to_shared(As);
    uint32_t sW = (uint32_t)__cvta_generic_to_shared(Ws);
    uint32_t aAddr = sA + 2u * (((w << 4) + ((quad & 1) << 3) + r8) * LDA + ((quad >> 1) << 3));
    uint32_t bAddr = sW + 2u * ((((quad & 1) << 3) + r8) * LDA + ((quad >> 1) << 3));

    float acc[16][4];
    #pragma unroll
    for (int j = 0; j < 16; j++) {
        #pragma unroll
        for (int q = 0; q < 4; q++) acc[j][q] = 0.f;
    }

    #pragma unroll
    for (int k0 = 0; k0 < 128; k0 += 16) {
        uint32_t am0, am1, am2, am3;
        ldsm4(am0, am1, am2, am3, aAddr + 2u * k0);
        #pragma unroll
        for (int nt = 0; nt < 8; nt++) {
            uint32_t bm0, bm1, bm2, bm3;
            ldsm4t(bm0, bm1, bm2, bm3, bAddr + 2u * (k0 * LDA + (nt << 4)));
            mma16816(acc[2 * nt],     am0, am1, am2, am3, bm0, bm1);
            mma16816(acc[2 * nt + 1], am0, am1, am2, am3, bm2, bm3);
        }
    }

    const int gq = lane >> 2, t2 = (lane & 3) << 1;
    const int r1 = row0 + (w << 4) + gq;
    const int r2 = r1 + 8;
    #pragma unroll
    for (int j = 0; j < 16; j++) {
        int col = (j << 3) + t2;
        if (r1 < N_NODES)
            *(__half2*)(g_bufB_h + (size_t)r1 * C + col) = __floats2half2_rn(acc[j][0], acc[j][1]);
        if (r2 < N_NODES)
            *(__half2*)(g_bufB_h + (size_t)r2 * C + col) = __floats2half2_rn(acc[j][2], acc[j][3]);
    }
}

// ---------------- aggregation: warp-per-node, 4 edges in flight ------------
__global__ void __launch_bounds__(256)
k_agg() {
    int warp = (blockIdx.x * 256 + threadIdx.x) >> 5;
    int lane = threadIdx.x & 31;
    if (warp >= N_NODES) return;
    const int d    = warp;
    const int half = lane >> 4;       // 0/1 : which edge of a pair
    const int fl   = lane & 15;       // feature group: 8 halfs at fl*8

    // self-loop row: issue early so it overlaps the gathers
    uint4 selfraw = __ldg((const uint4*)(g_bufB_h + (size_t)d * C) + fl);
    float dv = g_dinv[d];

    float acc[8];
    #pragma unroll
    for (int i = 0; i < 8; i++) acc[i] = 0.f;

    const int beg = g_off[d], end = g_off[d + 1];
    for (int base = beg; base < end; base += 32) {
        int idx = base + lane;
        int2 e = make_int2(0, 0);
        if (idx < end) e = g_csr[idx];
        int n = end - base; if (n > 32) n = 32;
        int j = 0;
        // unrolled: 2 pairs (4 edges) in flight -> MLP=2 per lane
        for (; j + 2 < n; j += 4) {
            int   sA = __shfl_sync(0xffffffffu, e.x, j + half);
            float wA = __shfl_sync(0xffffffffu, __int_as_float(e.y), j + half);
            int   sB = __shfl_sync(0xffffffffu, e.x, j + 2 + half);
            float wB = __shfl_sync(0xffffffffu, __int_as_float(e.y), j + 2 + half);
            uint4 ra = __ldg((const uint4*)(g_bufB_h + (size_t)sA * C) + fl);
            uint4 rb = __ldg((const uint4*)(g_bufB_h + (size_t)sB * C) + fl);
            fma8(acc, ra, wA);
            fma8(acc, rb, wB);
        }
        for (; j < n; j += 2) {
            int   s  = __shfl_sync(0xffffffffu, e.x, j + half);
            float cw = __shfl_sync(0xffffffffu, __int_as_float(e.y), j + half);
            uint4 rv = __ldg((const uint4*)(g_bufB_h + (size_t)s * C) + fl);
            fma8(acc, rv, cw);
        }
    }
    #pragma unroll
    for (int i = 0; i < 8; i++) acc[i] += __shfl_xor_sync(0xffffffffu, acc[i], 16);

    // self loop + store (lanes 0-15 carry the result)
    fma8(acc, selfraw, dv * dv);

    if (half == 0) {
        __half2 h0 = __floats2half2_rn(acc[0], acc[1]);
        __half2 h1 = __floats2half2_rn(acc[2], acc[3]);
        __half2 h2 = __floats2half2_rn(acc[4], acc[5]);
        __half2 h3 = __floats2half2_rn(acc[6], acc[7]);
        uint4 st;
        st.x = *(unsigned*)&h0; st.y = *(unsigned*)&h1;
        st.z = *(unsigned*)&h2; st.w = *(unsigned*)&h3;
        ((uint4*)(g_bufA_h + (size_t)d * C))[fl] = st;
    }
}

// ---------------- pooling: deterministic per-graph mean (512 thr) ----------
__global__ void __launch_bounds__(512)
k_pool(const float* __restrict__ b2) {
    int g = blockIdx.x;
    int t = threadIdx.x;
    int part = t >> 7;        // 0..3 : node-row stripe
    int f    = t & 127;       // feature index
    __shared__ float red[512];

    int beg = g_gstart[g], end = g_gstart[g + 1];
    float bb = b2[f];
    float acc = 0.f;
    for (int n = beg + part; n < end; n += 4) {
        float v = __half2float(g_bufA_h[(size_t)n * C + f]);
        acc += fmaxf(v + bb, 0.f);
    }
    red[t] = acc;
    __syncthreads();
    if (part == 0) {
        float tot = (red[f] + red[f + 128]) + (red[f + 256] + red[f + 384]);
        float inv = 1.0f / fmaxf((float)(end - beg), 1.0f);
        g_pooled[g * C + f] = tot * inv;
    }
}

// ---------------- head: single-step LSTM (c0=h0=0) + FC -------------------
__device__ __forceinline__ float sigmoidf_(float x) { return 1.0f / (1.0f + expf(-x)); }

__global__ void __launch_bounds__(128)
k_head(const float* __restrict__ W_ih, const float* __restrict__ b_ih,
       const float* __restrict__ b_hh, const float* __restrict__ W_fc,
       const float* __restrict__ b_fc, float* __restrict__ out)
{
    int g = blockIdx.x, t = threadIdx.x;
    __shared__ float p[C];
    __shared__ float r0s[C], r1s[C];

    p[t] = g_pooled[g * C + t];
    __syncthreads();

    float si = b_ih[t]       + b_hh[t];
    float sg = b_ih[256 + t] + b_hh[256 + t];
    float so = b_ih[384 + t] + b_hh[384 + t];
    const float* wi = W_ih + (size_t)t * C;
    const float* wg = W_ih + (size_t)(256 + t) * C;
    const float* wo = W_ih + (size_t)(384 + t) * C;
    #pragma unroll 4
    for (int k = 0; k < C; k++) {
        float pk = p[k];
        si = fmaf(pk, wi[k], si);
        sg = fmaf(pk, wg[k], sg);
        so = fmaf(pk, wo[k], so);
    }
    float c  = sigmoidf_(si) * tanhf(sg);
    float hn = sigmoidf_(so) * tanhf(c);

    r0s[t] = hn * W_fc[t];
    r1s[t] = hn * W_fc[C + t];
    __syncthreads();
    #pragma unroll
    for (int sft = 64; sft > 0; sft >>= 1) {
        if (t < sft) { r0s[t] += r0s[t + sft]; r1s[t] += r1s[t + sft]; }
        __syncthreads();
    }
    if (t == 0) {
        out[g * 2 + 0] = r0s[0] + b_fc[0];
        out[g * 2 + 1] = r1s[0] + b_fc[1];
    }
}

// ---------------- launch --------------------------------------------------
extern "C" void kernel_launch(void* const* d_in, const int* in_sizes, int n_in,
                              void* d_out, int out_size)
{
    const float* x     = (const float*)d_in[0];
    const int*   eidx  = (const int*)  d_in[1];
    const int*   batch = (const int*)  d_in[2];
    const float* W0    = (const float*)d_in[4];
    const float* b0    = (const float*)d_in[5];
    const float* W1    = (const float*)d_in[6];
    const float* b1    = (const float*)d_in[7];
    const float* W2    = (const float*)d_in[8];
    const float* b2    = (const float*)d_in[9];
    const float* W_ih  = (const float*)d_in[10];
    const float* b_ih  = (const float*)d_in[12];
    const float* b_hh  = (const float*)d_in[13];
    const float* W_fc  = (const float*)d_in[14];
    const float* b_fc  = (const float*)d_in[15];
    float* out = (float*)d_out;

    const int* src = eidx;
    const int* dst = eidx + N_EDGES;

    cudaFuncSetAttribute(k_gemm, cudaFuncAttributeMaxDynamicSharedMemorySize,
                         (int)GEMM_SMEM);

    const int nBlocks    = (N_NODES + 255) / 256;        // 391
    const int eBlocks    = (N_EDGES + 255) / 256;
    const int gemmBlocks = (N_NODES + GEMM_M - 1) / GEMM_M;  // 391
    const int aggBlocks  = (N_NODES * 32 + 255) / 256;

    // CSR build + weight conversion (once per launch)
    k_init<<<nBlocks, 256>>>();
    k_wconv<<<(3 * 4096 + 255) / 256, 256>>>(W0, W1, W2);
    k_deg_count<<<eBlocks, 256>>>(dst);
    k_scan1<<<SCAN_B, 256>>>(batch);
    k_scan2<<<1, 512>>>();
    k_scan3<<<SCAN_B, 256>>>();
    k_scatter<<<eBlocks, 256>>>(src, dst);

    // layer 0
    k_gemm<<<gemmBlocks, 512, GEMM_SMEM>>>(x, nullptr, 0, 1);
    k_agg<<<aggBlocks, 256>>>();
    // layer 1 (bias0+relu fused into GEMM A-load)
    k_gemm<<<gemmBlocks, 512, GEMM_SMEM>>>(nullptr, b0, 1, 0);
    k_agg<<<aggBlocks, 256>>>();
    // layer 2
    k_gemm<<<gemmBlocks, 512, GEMM_SMEM>>>(nullptr, b1, 2, 0);
    k_agg<<<aggBlocks, 256>>>();

    // pooling (bias2+relu fused) + head
    k_pool<<<G, 512>>>(b2);
    k_head<<<G, 128>>>(W_ih, b_ih, b_hh, W_fc, b_fc, out);
}

// round 15
// speedup vs baseline: 1.4653x; 1.4653x over previous
#include <cuda_runtime.h>
#include <cuda_fp16.h>
#include <cstdint>

// ---------------- problem constants ----------------
constexpr int N_NODES = 100000;
constexpr int N_EDGES = 1600000;
constexpr int C       = 128;      // feature width
constexpr int G       = 256;      // num graphs
constexpr int SCAN_B  = (N_NODES + 255) / 256;   // 391

// ---------------- scratch (static device globals) ----------
__device__ int    g_ideg[N_NODES];
__device__ int    g_off[N_NODES + 1];
__device__ int    g_epos[N_EDGES];                // per-edge slot within dst bucket
__device__ int    g_bsum[SCAN_B];
__device__ int    g_boff[SCAN_B];
__device__ float  g_dinv[N_NODES];
__device__ int2   g_csr[N_EDGES];                 // (src, w as float bits)
__device__ __half g_W_h[3 * C * C];               // fp16 weights (W0,W1,W2)
__device__ __half g_bufA_h[(size_t)N_NODES * C];  // agg output / GEMM input (fp16)
__device__ __half g_bufB_h[(size_t)N_NODES * C];  // GEMM output / gather operand (fp16)
__device__ float  g_pooled[G * C];
__device__ int    g_gstart[G + 1];

// ---------------- mma helpers ----------------
__device__ __forceinline__ void ldsm4(uint32_t& r0, uint32_t& r1, uint32_t& r2,
                                      uint32_t& r3, uint32_t addr) {
    asm volatile("ldmatrix.sync.aligned.m8n8.x4.shared.b16 {%0,%1,%2,%3}, [%4];"
                 : "=r"(r0), "=r"(r1), "=r"(r2), "=r"(r3) : "r"(addr));
}
__device__ __forceinline__ void ldsm4t(uint32_t& r0, uint32_t& r1, uint32_t& r2,
                                       uint32_t& r3, uint32_t addr) {
    asm volatile("ldmatrix.sync.aligned.m8n8.x4.trans.shared.b16 {%0,%1,%2,%3}, [%4];"
                 : "=r"(r0), "=r"(r1), "=r"(r2), "=r"(r3) : "r"(addr));
}
__device__ __forceinline__ void mma16816(float* d, uint32_t a0, uint32_t a1,
                                         uint32_t a2, uint32_t a3,
                                         uint32_t b0, uint32_t b1) {
    asm volatile("mma.sync.aligned.m16n8k16.row.col.f32.f16.f16.f32 "
                 "{%0,%1,%2,%3}, {%4,%5,%6,%7}, {%8,%9}, {%0,%1,%2,%3};"
                 : "+f"(d[0]), "+f"(d[1]), "+f"(d[2]), "+f"(d[3])
                 : "r"(a0), "r"(a1), "r"(a2), "r"(a3), "r"(b0), "r"(b1));
}

// fma of 8 halfs (uint4-packed) scaled by cw into acc[8]
__device__ __forceinline__ void fma8(float* acc, uint4 rv, float cw) {
    float2 v0 = __half22float2(*(__half2*)&rv.x);
    float2 v1 = __half22float2(*(__half2*)&rv.y);
    float2 v2 = __half22float2(*(__half2*)&rv.z);
    float2 v3 = __half22float2(*(__half2*)&rv.w);
    acc[0] = fmaf(cw, v0.x, acc[0]);
    acc[1] = fmaf(cw, v0.y, acc[1]);
    acc[2] = fmaf(cw, v1.x, acc[2]);
    acc[3] = fmaf(cw, v1.y, acc[3]);
    acc[4] = fmaf(cw, v2.x, acc[4]);
    acc[5] = fmaf(cw, v2.y, acc[5]);
    acc[6] = fmaf(cw, v3.x, acc[6]);
    acc[7] = fmaf(cw, v3.y, acc[7]);
}

// ---------------- weight pre-conversion (fp32 -> fp16, once) --------------
__global__ void __launch_bounds__(256)
k_wconv(const float* __restrict__ W0, const float* __restrict__ W1,
        const float* __restrict__ W2)
{
    int idx4 = blockIdx.x * 256 + threadIdx.x;     // float4 index, 3*4096 total
    if (idx4 >= 3 * 4096) return;
    int mat = idx4 >> 12;
    int loc = idx4 & 4095;
    const float* W = (mat == 0) ? W0 : (mat == 1) ? W1 : W2;
    float4 v = ((const float4*)W)[loc];
    __half2 h0 = __floats2half2_rn(v.x, v.y);
    __half2 h1 = __floats2half2_rn(v.z, v.w);
    uint2 st; st.x = *(unsigned*)&h0; st.y = *(unsigned*)&h1;
    *(uint2*)(g_W_h + mat * C * C + loc * 4) = st;
}

// ---------------- CSR build ----------------
__global__ void k_init() {
    int i = blockIdx.x * blockDim.x + threadIdx.x;
    if (i < N_NODES) g_ideg[i] = 0;
}

__global__ void k_deg_count(const int* __restrict__ dst) {
    int e = blockIdx.x * blockDim.x + threadIdx.x;
    if (e < N_EDGES) g_epos[e] = atomicAdd(&g_ideg[dst[e]], 1);
}

__global__ void __launch_bounds__(256) k_scan1() {
    __shared__ int sm[256];
    int t = threadIdx.x;
    int idx = blockIdx.x * 256 + t;
    int v = 0;
    if (idx < N_NODES) {
        v = g_ideg[idx];
        g_dinv[idx] = rsqrtf((float)(v + 1));
    }
    sm[t] = v;
    __syncthreads();
    #pragma unroll
    for (int s = 128; s > 0; s >>= 1) {
        if (t < s) sm[t] += sm[t + s];
        __syncthreads();
    }
    if (t == 0) g_bsum[blockIdx.x] = sm[0];
}

__global__ void __launch_bounds__(512) k_scan2(const int* __restrict__ batch) {
    __shared__ int sm[512];
    int t = threadIdx.x;
    sm[t] = (t < SCAN_B) ? g_bsum[t] : 0;
    __syncthreads();
    #pragma unroll
    for (int d = 1; d < 512; d <<= 1) {
        int v = (t >= d) ? sm[t - d] : 0;
        __syncthreads();
        sm[t] += v;
        __syncthreads();
    }
    if (t < SCAN_B) g_boff[t] = (t == 0) ? 0 : sm[t - 1];
    if (t <= G) {
        if (t == G) g_gstart[G] = N_NODES;
        else {
            int lo = 0, hi = N_NODES;
            while (lo < hi) {
                int mid = (lo + hi) >> 1;
                if (batch[mid] < t) lo = mid + 1; else hi = mid;
            }
            g_gstart[t] = lo;
        }
    }
}

__global__ void __launch_bounds__(256) k_scan3() {
    __shared__ int sm[256];
    int t = threadIdx.x;
    int idx = blockIdx.x * 256 + t;
    int v = (idx < N_NODES) ? g_ideg[idx] : 0;
    sm[t] = v;
    __syncthreads();
    #pragma unroll
    for (int d = 1; d < 256; d <<= 1) {
        int u = (t >= d) ? sm[t - d] : 0;
        __syncthreads();
        sm[t] += u;
        __syncthreads();
    }
    if (idx < N_NODES) g_off[idx] = g_boff[blockIdx.x] + sm[t] - v;
    if (idx == 0) g_off[N_NODES] = N_EDGES;
}

__global__ void k_scatter(const int* __restrict__ src, const int* __restrict__ dst) {
    int e = blockIdx.x * blockDim.x + threadIdx.x;
    if (e >= N_EDGES) return;
    int s = src[e], d = dst[e];
    int pos = g_off[d] + g_epos[e];
    g_csr[pos] = make_int2(s, __float_as_int(g_dinv[s] * g_dinv[d]));
}

// ---------------- tensor-core GEMM -----------------------------------------
constexpr int LDA    = 136;
constexpr int GEMM_M = 256;
constexpr size_t GEMM_SMEM = (size_t)((256 + 128) * LDA) * sizeof(__half);

__global__ void __launch_bounds__(512)
k_gemm(const float* __restrict__ Aext, const float* __restrict__ bias,
       int wsel, int use_ext)
{
    extern __shared__ __half smh[];
    __half* As = smh;               // [256][LDA]
    __half* Ws = smh + 256 * LDA;   // [128][LDA]

    const int tid  = threadIdx.x;
    const int row0 = blockIdx.x * GEMM_M;
    const __half* Wh = g_W_h + wsel * C * C;

    {
        const uint4* W4 = (const uint4*)Wh;
        #pragma unroll
        for (int i = 0; i < 4; i++) {
            int idx = i * 512 + tid;
            int h   = idx * 8;
            int k   = h >> 7, n = h & 127;
            *(uint4*)(Ws + k * LDA + n) = W4[idx];
        }
    }
    if (use_ext) {
        const float4* A4 = (const float4*)Aext;
        #pragma unroll
        for (int i = 0; i < 16; i++) {
            int f4 = i * 512 + tid;
            int f  = f4 * 4;
            int r  = f >> 7, c = f & 127;
            int row = row0 + r;
            float4 v = make_float4(0.f, 0.f, 0.f, 0.f);
            if (row < N_NODES) v = A4[(size_t)row * 32 + (c >> 2)];
            __half2 h0 = __floats2half2_rn(v.x, v.y);
            __half2 h1 = __floats2half2_rn(v.z, v.w);
            uint2 st; st.x = *(unsigned*)&h0; st.y = *(unsigned*)&h1;
            *(uint2*)(As + r * LDA + c) = st;
        }
    } else {
        #pragma unroll
        for (int i = 0; i < 16; i++) {
            int f4 = i * 512 + tid;
            int f  = f4 * 4;
            int r  = f >> 7, c = f & 127;
            int row = row0 + r;
            float4 v = make_float4(0.f, 0.f, 0.f, 0.f);
            if (row < N_NODES) {
                uint2 raw = *(const uint2*)(g_bufA_h + (size_t)row * C + c);
                float2 p0 = __half22float2(*(__half2*)&raw.x);
                float2 p1 = __half22float2(*(__half2*)&raw.y);
                float4 bb = *(const float4*)(bias + c);
                v.x = fmaxf(p0.x + bb.x, 0.f);
                v.y = fmaxf(p0.y + bb.y, 0.f);
                v.z = fmaxf(p1.x + bb.z, 0.f);
                v.w = fmaxf(p1.y + bb.w, 0.f);
            }
            __half2 h0 = __floats2half2_rn(v.x, v.y);
            __half2 h1 = __floats2half2_rn(v.z, v.w);
            uint2 st; st.x = *(unsigned*)&h0; st.y = *(unsigned*)&h1;
            *(uint2*)(As + r * LDA + c) = st;
        }
    }
    __syncthreads();

    const int w    = tid >> 5;
    const int lane = tid & 31;
    const int quad = lane >> 3, r8 = lane & 7;

    uint32_t sA = (uint32_t)__cvta_generic_to_shared(As);
    uint32_t sW = (uint32_t)__cvta_generic_to_shared(Ws);
    uint32_t aAddr = sA + 2u * (((w << 4) + ((quad & 1) << 3) + r8) * LDA + ((quad >> 1) << 3));
    uint32_t bAddr = sW + 2u * ((((quad & 1) << 3) + r8) * LDA + ((quad >> 1) << 3));

    float acc[16][4];
    #pragma unroll
    for (int j = 0; j < 16; j++) {
        #pragma unroll
        for (int q = 0; q < 4; q++) acc[j][q] = 0.f;
    }

    #pragma unroll
    for (int k0 = 0; k0 < 128; k0 += 16) {
        uint32_t am0, am1, am2, am3;
        ldsm4(am0, am1, am2, am3, aAddr + 2u * k0);
        #pragma unroll
        for (int nt = 0; nt < 8; nt++) {
            uint32_t bm0, bm1, bm2, bm3;
            ldsm4t(bm0, bm1, bm2, bm3, bAddr + 2u * (k0 * LDA + (nt << 4)));
            mma16816(acc[2 * nt],     am0, am1, am2, am3, bm0, bm1);
            mma16816(acc[2 * nt + 1], am0, am1, am2, am3, bm2, bm3);
        }
    }

    const int gq = lane >> 2, t2 = (lane & 3) << 1;
    const int r1 = row0 + (w << 4) + gq;
    const int r2 = r1 + 8;
    #pragma unroll
    for (int j = 0; j < 16; j++) {
        int col = (j << 3) + t2;
        if (r1 < N_NODES)
            *(__half2*)(g_bufB_h + (size_t)r1 * C + col) = __floats2half2_rn(acc[j][0], acc[j][1]);
        if (r2 < N_NODES)
            *(__half2*)(g_bufB_h + (size_t)r2 * C + col) = __floats2half2_rn(acc[j][2], acc[j][3]);
    }
}

// ---------------- aggregation: warp-per-node, 4 edges in flight ------------
__global__ void __launch_bounds__(256)
k_agg() {
    int warp = (blockIdx.x * 256 + threadIdx.x) >> 5;
    int lane = threadIdx.x & 31;
    if (warp >= N_NODES) return;
    const int d    = warp;
    const int half = lane >> 4;       // 0/1 : which edge of a pair
    const int fl   = lane & 15;       // feature group: 8 halfs at fl*8

    // self-loop row: issue early so it overlaps the gathers
    uint4 selfraw = __ldg((const uint4*)(g_bufB_h + (size_t)d * C) + fl);
    float dv = g_dinv[d];

    float acc[8];
    #pragma unroll
    for (int i = 0; i < 8; i++) acc[i] = 0.f;

    const int beg = g_off[d], end = g_off[d + 1];
    for (int base = beg; base < end; base += 32) {
        int idx = base + lane;
        int2 e = make_int2(0, 0);
        if (idx < end) e = g_csr[idx];
        int n = end - base; if (n > 32) n = 32;
        int j = 0;
        // unrolled: 2 pairs (4 edges) in flight -> MLP=2 per lane
        for (; j + 2 < n; j += 4) {
            int   sA = __shfl_sync(0xffffffffu, e.x, j + half);
            float wA = __shfl_sync(0xffffffffu, __int_as_float(e.y), j + half);
            int   sB = __shfl_sync(0xffffffffu, e.x, j + 2 + half);
            float wB = __shfl_sync(0xffffffffu, __int_as_float(e.y), j + 2 + half);
            uint4 ra = __ldg((const uint4*)(g_bufB_h + (size_t)sA * C) + fl);
            uint4 rb = __ldg((const uint4*)(g_bufB_h + (size_t)sB * C) + fl);
            fma8(acc, ra, wA);
            fma8(acc, rb, wB);
        }
        for (; j < n; j += 2) {
            int   s  = __shfl_sync(0xffffffffu, e.x, j + half);
            float cw = __shfl_sync(0xffffffffu, __int_as_float(e.y), j + half);
            uint4 rv = __ldg((const uint4*)(g_bufB_h + (size_t)s * C) + fl);
            fma8(acc, rv, cw);
        }
    }
    #pragma unroll
    for (int i = 0; i < 8; i++) acc[i] += __shfl_xor_sync(0xffffffffu, acc[i], 16);

    // self loop + store (lanes 0-15 carry the result)
    fma8(acc, selfraw, dv * dv);

    if (half == 0) {
        __half2 h0 = __floats2half2_rn(acc[0], acc[1]);
        __half2 h1 = __floats2half2_rn(acc[2], acc[3]);
        __half2 h2 = __floats2half2_rn(acc[4], acc[5]);
        __half2 h3 = __floats2half2_rn(acc[6], acc[7]);
        uint4 st;
        st.x = *(unsigned*)&h0; st.y = *(unsigned*)&h1;
        st.z = *(unsigned*)&h2; st.w = *(unsigned*)&h3;
        ((uint4*)(g_bufA_h + (size_t)d * C))[fl] = st;
    }
}

// ---------------- pooling: deterministic per-graph mean (512 thr) ----------
__global__ void __launch_bounds__(512)
k_pool(const float* __restrict__ b2) {
    int g = blockIdx.x;
    int t = threadIdx.x;
    int part = t >> 7;        // 0..3 : node-row stripe
    int f    = t & 127;       // feature index
    __shared__ float red[512];

    int beg = g_gstart[g], end = g_gstart[g + 1];
    float bb = b2[f];
    float acc = 0.f;
    for (int n = beg + part; n < end; n += 4) {
        float v = __half2float(g_bufA_h[(size_t)n * C + f]);
        acc += fmaxf(v + bb, 0.f);
    }
    red[t] = acc;
    __syncthreads();
    if (part == 0) {
        float tot = (red[f] + red[f + 128]) + (red[f + 256] + red[f + 384]);
        float inv = 1.0f / fmaxf((float)(end - beg), 1.0f);
        g_pooled[g * C + f] = tot * inv;
    }
}

// ---------------- head: single-step LSTM (c0=h0=0) + FC -------------------
__device__ __forceinline__ float sigmoidf_(float x) { return 1.0f / (1.0f + expf(-x)); }

__global__ void __launch_bounds__(128)
k_head(const float* __restrict__ W_ih, const float* __restrict__ b_ih,
       const float* __restrict__ b_hh, const float* __restrict__ W_fc,
       const float* __restrict__ b_fc, float* __restrict__ out)
{
    int g = blockIdx.x, t = threadIdx.x;
    __shared__ float p[C];
    __shared__ float r0s[C], r1s[C];

    p[t] = g_pooled[g * C + t];
    __syncthreads();

    float si = b_ih[t]       + b_hh[t];
    float sg = b_ih[256 + t] + b_hh[256 + t];
    float so = b_ih[384 + t] + b_hh[384 + t];
    const float* wi = W_ih + (size_t)t * C;
    const float* wg = W_ih + (size_t)(256 + t) * C;
    const float* wo = W_ih + (size_t)(384 + t) * C;
    #pragma unroll 4
    for (int k = 0; k < C; k++) {
        float pk = p[k];
        si = fmaf(pk, wi[k], si);
        sg = fmaf(pk, wg[k], sg);
        so = fmaf(pk, wo[k], so);
    }
    float c  = sigmoidf_(si) * tanhf(sg);
    float hn = sigmoidf_(so) * tanhf(c);

    r0s[t] = hn * W_fc[t];
    r1s[t] = hn * W_fc[C + t];
    __syncthreads();
    #pragma unroll
    for (int sft = 64; sft > 0; sft >>= 1) {
        if (t < sft) { r0s[t] += r0s[t + sft]; r1s[t] += r1s[t + sft]; }
        __syncthreads();
    }
    if (t == 0) {
        out[g * 2 + 0] = r0s[0] + b_fc[0];
        out[g * 2 + 1] = r1s[0] + b_fc[1];
    }
}

// ---------------- launch --------------------------------------------------
extern "C" void kernel_launch(void* const* d_in, const int* in_sizes, int n_in,
                              void* d_out, int out_size)
{
    const float* x     = (const float*)d_in[0];
    const int*   eidx  = (const int*)  d_in[1];
    const int*   batch = (const int*)  d_in[2];
    const float* W0    = (const float*)d_in[4];
    const float* b0    = (const float*)d_in[5];
    const float* W1    = (const float*)d_in[6];
    const float* b1    = (const float*)d_in[7];
    const float* W2    = (const float*)d_in[8];
    const float* b2    = (const float*)d_in[9];
    const float* W_ih  = (const float*)d_in[10];
    const float* b_ih  = (const float*)d_in[12];
    const float* b_hh  = (const float*)d_in[13];
    const float* W_fc  = (const float*)d_in[14];
    const float* b_fc  = (const float*)d_in[15];
    float* out = (float*)d_out;

    const int* src = eidx;
    const int* dst = eidx + N_EDGES;

    cudaFuncSetAttribute(k_gemm, cudaFuncAttributeMaxDynamicSharedMemorySize,
                         (int)GEMM_SMEM);

    const int nBlocks    = (N_NODES + 255) / 256;        // 391
    const int eBlocks    = (N_EDGES + 255) / 256;
    const int gemmBlocks = (N_NODES + GEMM_M - 1) / GEMM_M;  // 391
    const int aggBlocks  = (N_NODES * 32 + 255) / 256;

    // CSR build + weight conversion (once per launch)
    k_init<<<nBlocks, 256>>>();
    k_wconv<<<(3 * 4096 + 255) / 256, 256>>>(W0, W1, W2);
    k_deg_count<<<eBlocks, 256>>>(dst);
    k_scan1<<<SCAN_B, 256>>>();
    k_scan2<<<1, 512>>>(batch);
    k_scan3<<<SCAN_B, 256>>>();
    k_scatter<<<eBlocks, 256>>>(src, dst);

    // layer 0
    k_gemm<<<gemmBlocks, 512, GEMM_SMEM>>>(x, nullptr, 0, 1);
    k_agg<<<aggBlocks, 256>>>();
    // layer 1 (bias0+relu fused into GEMM A-load)
    k_gemm<<<gemmBlocks, 512, GEMM_SMEM>>>(nullptr, b0, 1, 0);
    k_agg<<<aggBlocks, 256>>>();
    // layer 2
    k_gemm<<<gemmBlocks, 512, GEMM_SMEM>>>(nullptr, b1, 2, 0);
    k_agg<<<aggBlocks, 256>>>();

    // pooling (bias2+relu fused) + head
    k_pool<<<G, 512>>>(b2);
    k_head<<<G, 128>>>(W_ih, b_ih, b_hh, W_fc, b_fc, out);
}

// round 16
// speedup vs baseline: 1.5182x; 1.0361x over previous
#include <cuda_runtime.h>
#include <cuda_fp16.h>
#include <cstdint>

// ---------------- problem constants ----------------
constexpr int N_NODES = 100000;
constexpr int N_EDGES = 1600000;
constexpr int C       = 128;      // feature width
constexpr int G       = 256;      // num graphs
constexpr int SCAN_B  = (N_NODES + 255) / 256;   // 391

// ---------------- scratch (static device globals) ----------
__device__ int    g_ideg[N_NODES];
__device__ int    g_off[N_NODES + 1];
__device__ int    g_epos[N_EDGES];                // per-edge slot within dst bucket
__device__ int    g_bsum[SCAN_B];
__device__ int    g_boff[SCAN_B];
__device__ float  g_dinv[N_NODES];
__device__ int2   g_csr[N_EDGES];                 // (src, w as float bits)
__device__ __half g_W_h[3 * C * C];               // fp16 weights (W0,W1,W2)
__device__ __half g_bufA_h[(size_t)N_NODES * C];  // agg output / GEMM input (fp16)
__device__ __half g_bufB_h[(size_t)N_NODES * C];  // GEMM output / gather operand (fp16)
__device__ float  g_pooled[G * C];
__device__ int    g_gstart[G + 1];

// ---------------- mma helpers ----------------
__device__ __forceinline__ void ldsm4(uint32_t& r0, uint32_t& r1, uint32_t& r2,
                                      uint32_t& r3, uint32_t addr) {
    asm volatile("ldmatrix.sync.aligned.m8n8.x4.shared.b16 {%0,%1,%2,%3}, [%4];"
                 : "=r"(r0), "=r"(r1), "=r"(r2), "=r"(r3) : "r"(addr));
}
__device__ __forceinline__ void ldsm4t(uint32_t& r0, uint32_t& r1, uint32_t& r2,
                                       uint32_t& r3, uint32_t addr) {
    asm volatile("ldmatrix.sync.aligned.m8n8.x4.trans.shared.b16 {%0,%1,%2,%3}, [%4];"
                 : "=r"(r0), "=r"(r1), "=r"(r2), "=r"(r3) : "r"(addr));
}
__device__ __forceinline__ void mma16816(float* d, uint32_t a0, uint32_t a1,
                                         uint32_t a2, uint32_t a3,
                                         uint32_t b0, uint32_t b1) {
    asm volatile("mma.sync.aligned.m16n8k16.row.col.f32.f16.f16.f32 "
                 "{%0,%1,%2,%3}, {%4,%5,%6,%7}, {%8,%9}, {%0,%1,%2,%3};"
                 : "+f"(d[0]), "+f"(d[1]), "+f"(d[2]), "+f"(d[3])
                 : "r"(a0), "r"(a1), "r"(a2), "r"(a3), "r"(b0), "r"(b1));
}

// fma of 8 halfs (uint4-packed) scaled by cw into acc[8]
__device__ __forceinline__ void fma8(float* acc, uint4 rv, float cw) {
    float2 v0 = __half22float2(*(__half2*)&rv.x);
    float2 v1 = __half22float2(*(__half2*)&rv.y);
    float2 v2 = __half22float2(*(__half2*)&rv.z);
    float2 v3 = __half22float2(*(__half2*)&rv.w);
    acc[0] = fmaf(cw, v0.x, acc[0]);
    acc[1] = fmaf(cw, v0.y, acc[1]);
    acc[2] = fmaf(cw, v1.x, acc[2]);
    acc[3] = fmaf(cw, v1.y, acc[3]);
    acc[4] = fmaf(cw, v2.x, acc[4]);
    acc[5] = fmaf(cw, v2.y, acc[5]);
    acc[6] = fmaf(cw, v3.x, acc[6]);
    acc[7] = fmaf(cw, v3.y, acc[7]);
}

// ---------------- weight pre-conversion (fp32 -> fp16, once) --------------
__global__ void __launch_bounds__(256)
k_wconv(const float* __restrict__ W0, const float* __restrict__ W1,
        const float* __restrict__ W2)
{
    int idx4 = blockIdx.x * 256 + threadIdx.x;     // float4 index, 3*4096 total
    if (idx4 >= 3 * 4096) return;
    int mat = idx4 >> 12;
    int loc = idx4 & 4095;
    const float* W = (mat == 0) ? W0 : (mat == 1) ? W1 : W2;
    float4 v = ((const float4*)W)[loc];
    __half2 h0 = __floats2half2_rn(v.x, v.y);
    __half2 h1 = __floats2half2_rn(v.z, v.w);
    uint2 st; st.x = *(unsigned*)&h0; st.y = *(unsigned*)&h1;
    *(uint2*)(g_W_h + mat * C * C + loc * 4) = st;
}

// ---------------- CSR build ----------------
__global__ void k_init() {
    int i = blockIdx.x * blockDim.x + threadIdx.x;
    if (i < N_NODES) g_ideg[i] = 0;
}

__global__ void k_deg_count(const int* __restrict__ dst) {
    int e = blockIdx.x * blockDim.x + threadIdx.x;
    if (e < N_EDGES) g_epos[e] = atomicAdd(&g_ideg[dst[e]], 1);
}

__global__ void __launch_bounds__(256) k_scan1() {
    __shared__ int sm[256];
    int t = threadIdx.x;
    int idx = blockIdx.x * 256 + t;
    int v = 0;
    if (idx < N_NODES) {
        v = g_ideg[idx];
        g_dinv[idx] = rsqrtf((float)(v + 1));
    }
    sm[t] = v;
    __syncthreads();
    #pragma unroll
    for (int s = 128; s > 0; s >>= 1) {
        if (t < s) sm[t] += sm[t + s];
        __syncthreads();
    }
    if (t == 0) g_bsum[blockIdx.x] = sm[0];
}

__global__ void __launch_bounds__(512) k_scan2(const int* __restrict__ batch) {
    __shared__ int sm[512];
    int t = threadIdx.x;
    sm[t] = (t < SCAN_B) ? g_bsum[t] : 0;
    __syncthreads();
    #pragma unroll
    for (int d = 1; d < 512; d <<= 1) {
        int v = (t >= d) ? sm[t - d] : 0;
        __syncthreads();
        sm[t] += v;
        __syncthreads();
    }
    if (t < SCAN_B) g_boff[t] = (t == 0) ? 0 : sm[t - 1];
    if (t <= G) {
        if (t == G) g_gstart[G] = N_NODES;
        else {
            int lo = 0, hi = N_NODES;
            while (lo < hi) {
                int mid = (lo + hi) >> 1;
                if (batch[mid] < t) lo = mid + 1; else hi = mid;
            }
            g_gstart[t] = lo;
        }
    }
}

__global__ void __launch_bounds__(256) k_scan3() {
    __shared__ int sm[256];
    int t = threadIdx.x;
    int idx = blockIdx.x * 256 + t;
    int v = (idx < N_NODES) ? g_ideg[idx] : 0;
    sm[t] = v;
    __syncthreads();
    #pragma unroll
    for (int d = 1; d < 256; d <<= 1) {
        int u = (t >= d) ? sm[t - d] : 0;
        __syncthreads();
        sm[t] += u;
        __syncthreads();
    }
    if (idx < N_NODES) g_off[idx] = g_boff[blockIdx.x] + sm[t] - v;
    if (idx == 0) g_off[N_NODES] = N_EDGES;
}

__global__ void k_scatter(const int* __restrict__ src, const int* __restrict__ dst) {
    int e = blockIdx.x * blockDim.x + threadIdx.x;
    if (e >= N_EDGES) return;
    int s = src[e], d = dst[e];
    int pos = g_off[d] + g_epos[e];
    g_csr[pos] = make_int2(s, __float_as_int(g_dinv[s] * g_dinv[d]));
}

// ---------------- tensor-core GEMM -----------------------------------------
constexpr int LDA    = 136;
constexpr int GEMM_M = 256;
constexpr size_t GEMM_SMEM = (size_t)((256 + 128) * LDA) * sizeof(__half);

__global__ void __launch_bounds__(512)
k_gemm(const float* __restrict__ Aext, const float* __restrict__ bias,
       int wsel, int use_ext)
{
    extern __shared__ __half smh[];
    __half* As = smh;               // [256][LDA]
    __half* Ws = smh + 256 * LDA;   // [128][LDA]

    const int tid  = threadIdx.x;
    const int row0 = blockIdx.x * GEMM_M;
    const __half* Wh = g_W_h + wsel * C * C;

    {
        const uint4* W4 = (const uint4*)Wh;
        #pragma unroll
        for (int i = 0; i < 4; i++) {
            int idx = i * 512 + tid;
            int h   = idx * 8;
            int k   = h >> 7, n = h & 127;
            *(uint4*)(Ws + k * LDA + n) = W4[idx];
        }
    }
    if (use_ext) {
        const float4* A4 = (const float4*)Aext;
        #pragma unroll
        for (int i = 0; i < 16; i++) {
            int f4 = i * 512 + tid;
            int f  = f4 * 4;
            int r  = f >> 7, c = f & 127;
            int row = row0 + r;
            float4 v = make_float4(0.f, 0.f, 0.f, 0.f);
            if (row < N_NODES) v = A4[(size_t)row * 32 + (c >> 2)];
            __half2 h0 = __floats2half2_rn(v.x, v.y);
            __half2 h1 = __floats2half2_rn(v.z, v.w);
            uint2 st; st.x = *(unsigned*)&h0; st.y = *(unsigned*)&h1;
            *(uint2*)(As + r * LDA + c) = st;
        }
    } else {
        #pragma unroll
        for (int i = 0; i < 16; i++) {
            int f4 = i * 512 + tid;
            int f  = f4 * 4;
            int r  = f >> 7, c = f & 127;
            int row = row0 + r;
            float4 v = make_float4(0.f, 0.f, 0.f, 0.f);
            if (row < N_NODES) {
                uint2 raw = *(const uint2*)(g_bufA_h + (size_t)row * C + c);
                float2 p0 = __half22float2(*(__half2*)&raw.x);
                float2 p1 = __half22float2(*(__half2*)&raw.y);
                float4 bb = *(const float4*)(bias + c);
                v.x = fmaxf(p0.x + bb.x, 0.f);
                v.y = fmaxf(p0.y + bb.y, 0.f);
                v.z = fmaxf(p1.x + bb.z, 0.f);
                v.w = fmaxf(p1.y + bb.w, 0.f);
            }
            __half2 h0 = __floats2half2_rn(v.x, v.y);
            __half2 h1 = __floats2half2_rn(v.z, v.w);
            uint2 st; st.x = *(unsigned*)&h0; st.y = *(unsigned*)&h1;
            *(uint2*)(As + r * LDA + c) = st;
        }
    }
    __syncthreads();

    const int w    = tid >> 5;
    const int lane = tid & 31;
    const int quad = lane >> 3, r8 = lane & 7;

    uint32_t sA = (uint32_t)__cvta_generic_to_shared(As);
    uint32_t sW = (uint32_t)__cvta_generic_to_shared(Ws);
    uint32_t aAddr = sA + 2u * (((w << 4) + ((quad & 1) << 3) + r8) * LDA + ((quad >> 1) << 3));
    uint32_t bAddr = sW + 2u * ((((quad & 1) << 3) + r8) * LDA + ((quad >> 1) << 3));

    float acc[16][4];
    #pragma unroll
    for (int j = 0; j < 16; j++) {
        #pragma unroll
        for (int q = 0; q < 4; q++) acc[j][q] = 0.f;
    }

    #pragma unroll
    for (int k0 = 0; k0 < 128; k0 += 16) {
        uint32_t am0, am1, am2, am3;
        ldsm4(am0, am1, am2, am3, aAddr + 2u * k0);
        #pragma unroll
        for (int nt = 0; nt < 8; nt++) {
            uint32_t bm0, bm1, bm2, bm3;
            ldsm4t(bm0, bm1, bm2, bm3, bAddr + 2u * (k0 * LDA + (nt << 4)));
            mma16816(acc[2 * nt],     am0, am1, am2, am3, bm0, bm1);
            mma16816(acc[2 * nt + 1], am0, am1, am2, am3, bm2, bm3);
        }
    }

    const int gq = lane >> 2, t2 = (lane & 3) << 1;
    const int r1 = row0 + (w << 4) + gq;
    const int r2 = r1 + 8;
    #pragma unroll
    for (int j = 0; j < 16; j++) {
        int col = (j << 3) + t2;
        if (r1 < N_NODES)
            *(__half2*)(g_bufB_h + (size_t)r1 * C + col) = __floats2half2_rn(acc[j][0], acc[j][1]);
        if (r2 < N_NODES)
            *(__half2*)(g_bufB_h + (size_t)r2 * C + col) = __floats2half2_rn(acc[j][2], acc[j][3]);
    }
}

// ---------------- aggregation: warp-per-node, 4 edges in flight ------------
__global__ void __launch_bounds__(256)
k_agg() {
    int warp = (blockIdx.x * 256 + threadIdx.x) >> 5;
    int lane = threadIdx.x & 31;
    if (warp >= N_NODES) return;
    const int d    = warp;
    const int half = lane >> 4;       // 0/1 : which edge of a pair
    const int fl   = lane & 15;       // feature group: 8 halfs at fl*8

    // self-loop row: issue early so it overlaps the gathers
    uint4 selfraw = __ldg((const uint4*)(g_bufB_h + (size_t)d * C) + fl);
    float dv = g_dinv[d];

    float acc[8];
    #pragma unroll
    for (int i = 0; i < 8; i++) acc[i] = 0.f;

    const int beg = g_off[d], end = g_off[d + 1];
    for (int base = beg; base < end; base += 32) {
        int idx = base + lane;
        int2 e = make_int2(0, 0);
        if (idx < end) e = g_csr[idx];
        int n = end - base; if (n > 32) n = 32;
        int j = 0;
        // unrolled: 2 pairs (4 edges) in flight -> MLP=2 per lane
        for (; j + 2 < n; j += 4) {
            int   sA = __shfl_sync(0xffffffffu, e.x, j + half);
            float wA = __shfl_sync(0xffffffffu, __int_as_float(e.y), j + half);
            int   sB = __shfl_sync(0xffffffffu, e.x, j + 2 + half);
            float wB = __shfl_sync(0xffffffffu, __int_as_float(e.y), j + 2 + half);
            uint4 ra = __ldg((const uint4*)(g_bufB_h + (size_t)sA * C) + fl);
            uint4 rb = __ldg((const uint4*)(g_bufB_h + (size_t)sB * C) + fl);
            fma8(acc, ra, wA);
            fma8(acc, rb, wB);
        }
        for (; j < n; j += 2) {
            int   s  = __shfl_sync(0xffffffffu, e.x, j + half);
            float cw = __shfl_sync(0xffffffffu, __int_as_float(e.y), j + half);
            uint4 rv = __ldg((const uint4*)(g_bufB_h + (size_t)s * C) + fl);
            fma8(acc, rv, cw);
        }
    }
    #pragma unroll
    for (int i = 0; i < 8; i++) acc[i] += __shfl_xor_sync(0xffffffffu, acc[i], 16);

    // self loop + store (lanes 0-15 carry the result)
    fma8(acc, selfraw, dv * dv);

    if (half == 0) {
        __half2 h0 = __floats2half2_rn(acc[0], acc[1]);
        __half2 h1 = __floats2half2_rn(acc[2], acc[3]);
        __half2 h2 = __floats2half2_rn(acc[4], acc[5]);
        __half2 h3 = __floats2half2_rn(acc[6], acc[7]);
        uint4 st;
        st.x = *(unsigned*)&h0; st.y = *(unsigned*)&h1;
        st.z = *(unsigned*)&h2; st.w = *(unsigned*)&h3;
        ((uint4*)(g_bufA_h + (size_t)d * C))[fl] = st;
    }
}

// ---------------- pooling: deterministic per-graph mean (512 thr) ----------
__global__ void __launch_bounds__(512)
k_pool(const float* __restrict__ b2) {
    int g = blockIdx.x;
    int t = threadIdx.x;
    int part = t >> 7;        // 0..3 : node-row stripe
    int f    = t & 127;       // feature index
    __shared__ float red[512];

    int beg = g_gstart[g], end = g_gstart[g + 1];
    float bb = b2[f];
    float acc = 0.f;
    for (int n = beg + part; n < end; n += 4) {
        float v = __half2float(g_bufA_h[(size_t)n * C + f]);
        acc += fmaxf(v + bb, 0.f);
    }
    red[t] = acc;
    __syncthreads();
    if (part == 0) {
        float tot = (red[f] + red[f + 128]) + (red[f + 256] + red[f + 384]);
        float inv = 1.0f / fmaxf((float)(end - beg), 1.0f);
        g_pooled[g * C + f] = tot * inv;
    }
}

// ---------------- head: single-step LSTM (c0=h0=0) + FC -------------------
__device__ __forceinline__ float sigmoidf_(float x) { return 1.0f / (1.0f + expf(-x)); }

__global__ void __launch_bounds__(128)
k_head(const float* __restrict__ W_ih, const float* __restrict__ b_ih,
       const float* __restrict__ b_hh, const float* __restrict__ W_fc,
       const float* __restrict__ b_fc, float* __restrict__ out)
{
    int g = blockIdx.x, t = threadIdx.x;
    __shared__ float p[C];
    __shared__ float r0s[C], r1s[C];

    p[t] = g_pooled[g * C + t];
    __syncthreads();

    float si = b_ih[t]       + b_hh[t];
    float sg = b_ih[256 + t] + b_hh[256 + t];
    float so = b_ih[384 + t] + b_hh[384 + t];
    const float* wi = W_ih + (size_t)t * C;
    const float* wg = W_ih + (size_t)(256 + t) * C;
    const float* wo = W_ih + (size_t)(384 + t) * C;
    #pragma unroll 4
    for (int k = 0; k < C; k++) {
        float pk = p[k];
        si = fmaf(pk, wi[k], si);
        sg = fmaf(pk, wg[k], sg);
        so = fmaf(pk, wo[k], so);
    }
    float c  = sigmoidf_(si) * tanhf(sg);
    float hn = sigmoidf_(so) * tanhf(c);

    r0s[t] = hn * W_fc[t];
    r1s[t] = hn * W_fc[C + t];
    __syncthreads();
    #pragma unroll
    for (int sft = 64; sft > 0; sft >>= 1) {
        if (t < sft) { r0s[t] += r0s[t + sft]; r1s[t] += r1s[t + sft]; }
        __syncthreads();
    }
    if (t == 0) {
        out[g * 2 + 0] = r0s[0] + b_fc[0];
        out[g * 2 + 1] = r1s[0] + b_fc[1];
    }
}

// ---------------- launch --------------------------------------------------
extern "C" void kernel_launch(void* const* d_in, const int* in_sizes, int n_in,
                              void* d_out, int out_size)
{
    const float* x     = (const float*)d_in[0];
    const int*   eidx  = (const int*)  d_in[1];
    const int*   batch = (const int*)  d_in[2];
    const float* W0    = (const float*)d_in[4];
    const float* b0    = (const float*)d_in[5];
    const float* W1    = (const float*)d_in[6];
    const float* b1    = (const float*)d_in[7];
    const float* W2    = (const float*)d_in[8];
    const float* b2    = (const float*)d_in[9];
    const float* W_ih  = (const float*)d_in[10];
    const float* b_ih  = (const float*)d_in[12];
    const float* b_hh  = (const float*)d_in[13];
    const float* W_fc  = (const float*)d_in[14];
    const float* b_fc  = (const float*)d_in[15];
    float* out = (float*)d_out;

    const int* src = eidx;
    const int* dst = eidx + N_EDGES;

    cudaFuncSetAttribute(k_gemm, cudaFuncAttributeMaxDynamicSharedMemorySize,
                         (int)GEMM_SMEM);

    // side stream + events for build/GEMM overlap (host objects, created once;
    // no device allocation — identical launch sequence every call)
    static cudaStream_t sB = nullptr;
    static cudaEvent_t evFork = nullptr, evJoin = nullptr;
    if (sB == nullptr) {
        cudaStreamCreateWithFlags(&sB, cudaStreamNonBlocking);
        cudaEventCreateWithFlags(&evFork, cudaEventDisableTiming);
        cudaEventCreateWithFlags(&evJoin, cudaEventDisableTiming);
    }

    const int nBlocks    = (N_NODES + 255) / 256;        // 391
    const int eBlocks    = (N_EDGES + 255) / 256;
    const int gemmBlocks = (N_NODES + GEMM_M - 1) / GEMM_M;  // 391
    const int aggBlocks  = (N_NODES * 32 + 255) / 256;

    // fork: CSR build chain on side stream, concurrent with wconv + layer-0 GEMM
    cudaEventRecord(evFork, 0);
    cudaStreamWaitEvent(sB, evFork, 0);

    k_init<<<nBlocks, 256, 0, sB>>>();
    k_deg_count<<<eBlocks, 256, 0, sB>>>(dst);
    k_scan1<<<SCAN_B, 256, 0, sB>>>();
    k_scan2<<<1, 512, 0, sB>>>(batch);
    k_scan3<<<SCAN_B, 256, 0, sB>>>();
    k_scatter<<<eBlocks, 256, 0, sB>>>(src, dst);
    cudaEventRecord(evJoin, sB);

    // main stream: weight conversion + layer-0 GEMM (independent of CSR)
    k_wconv<<<(3 * 4096 + 255) / 256, 256>>>(W0, W1, W2);
    k_gemm<<<gemmBlocks, 512, GEMM_SMEM>>>(x, nullptr, 0, 1);

    // join: agg0 needs both the GEMM output and the CSR
    cudaStreamWaitEvent(0, evJoin, 0);

    k_agg<<<aggBlocks, 256>>>();
    // layer 1 (bias0+relu fused into GEMM A-load)
    k_gemm<<<gemmBlocks, 512, GEMM_SMEM>>>(nullptr, b0, 1, 0);
    k_agg<<<aggBlocks, 256>>>();
    // layer 2
    k_gemm<<<gemmBlocks, 512, GEMM_SMEM>>>(nullptr, b1, 2, 0);
    k_agg<<<aggBlocks, 256>>>();

    // pooling (bias2+relu fused) + head
    k_pool<<<G, 512>>>(b2);
    k_head<<<G, 128>>>(W_ih, b_ih, b_hh, W_fc, b_fc, out);
}